// round 1
// baseline (speedup 1.0000x reference)
#include <cuda_runtime.h>
#include <math.h>

#define EPSF 1e-8f
#define TOLF 1e-6f
#define MAXV 24
#define NBLK 2048

__device__ float g_partials[NBLK];

// Decoded 2D box: (cx, cy, w, l, theta) + z extent + volume
struct DecBox {
    float cx, cy, w, l, th;
    float zmin, zmax, vol;
};

__device__ __forceinline__ DecBox decode(const float* d) {
    // d = (d_x-, d_y-, d_z-, d_x+, d_y+, d_z+, theta), loc = 0
    float d0 = d[0], d1 = d[1], d2 = d[2], d3 = d[3], d4 = d[4], d5 = d[5];
    float th = d[6];
    DecBox b;
    b.w  = d0 + d3;
    b.l  = d1 + d4;
    float h = d2 + d5;
    float ox = (d3 - d0) * 0.5f;
    float oy = (d4 - d1) * 0.5f;
    float oz = (d5 - d2) * 0.5f;
    float c = cosf(th), s = sinf(th);
    b.cx = ox * c - oy * s;
    b.cy = ox * s + oy * c;
    float cz = oz;
    b.th = th;
    b.zmin = cz - h * 0.5f;
    b.zmax = cz + h * 0.5f;
    b.vol  = b.w * b.l * h;
    return b;
}

__device__ __forceinline__ void corners4(const DecBox& b, float* X, float* Y) {
    const float xs[4] = {0.5f, -0.5f, -0.5f, 0.5f};
    const float ys[4] = {0.5f, 0.5f, -0.5f, -0.5f};
    float c = cosf(b.th), s = sinf(b.th);
#pragma unroll
    for (int i = 0; i < 4; i++) {
        float x4 = xs[i] * b.w;
        float y4 = ys[i] * b.l;
        X[i] = x4 * c - y4 * s + b.cx;
        Y[i] = x4 * s + y4 * c + b.cy;
    }
}

// point-in-box test per reference box1_in_box2
__device__ __forceinline__ void in_box(const float* px, const float* py,
                                       const float* qx, const float* qy,
                                       bool* m) {
    float ax = qx[0], ay = qy[0];
    float abx = qx[1] - ax, aby = qy[1] - ay;
    float adx = qx[3] - ax, ady = qy[3] - ay;
    float ab2 = abx * abx + aby * aby;
    float ad2 = adx * adx + ady * ady;
#pragma unroll
    for (int i = 0; i < 4; i++) {
        float amx = px[i] - ax, amy = py[i] - ay;
        float pab = (abx * amx + aby * amy) / ab2;
        float pad = (adx * amx + ady * amy) / ad2;
        m[i] = (pab > -TOLF) && (pab < 1.0f + TOLF) &&
               (pad > -TOLF) && (pad < 1.0f + TOLF);
    }
}

__global__ void __launch_bounds__(256)
riou_kernel(const float* __restrict__ pred,
            const float* __restrict__ target,
            const float* __restrict__ weight,
            int n) {
    float acc = 0.0f;
    for (int i = blockIdx.x * blockDim.x + threadIdx.x; i < n;
         i += gridDim.x * blockDim.x) {
        DecBox b1 = decode(pred + (size_t)i * 7);
        DecBox b2 = decode(target + (size_t)i * 7);

        float c1x[4], c1y[4], c2x[4], c2y[4];
        corners4(b1, c1x, c1y);
        corners4(b2, c2x, c2y);

        // gather masked vertices (order: c1, c2, then 16 intersections i-major)
        float vx[MAXV], vy[MAXV];
        int nv = 0;
        float sx = 0.0f, sy = 0.0f;

        bool m12[4], m21[4];
        in_box(c1x, c1y, c2x, c2y, m12);
        in_box(c2x, c2y, c1x, c1y, m21);
#pragma unroll
        for (int k = 0; k < 4; k++)
            if (m12[k]) { vx[nv] = c1x[k]; vy[nv] = c1y[k]; sx += c1x[k]; sy += c1y[k]; nv++; }
#pragma unroll
        for (int k = 0; k < 4; k++)
            if (m21[k]) { vx[nv] = c2x[k]; vy[nv] = c2y[k]; sx += c2x[k]; sy += c2y[k]; nv++; }

        // 16 edge-edge intersections
#pragma unroll
        for (int a = 0; a < 4; a++) {
            float x1 = c1x[a], y1 = c1y[a];
            float x2 = c1x[(a + 1) & 3], y2 = c1y[(a + 1) & 3];
            float ex = x2 - x1, ey = y2 - y1;
#pragma unroll
            for (int b = 0; b < 4; b++) {
                float x3 = c2x[b], y3 = c2y[b];
                float x4 = c2x[(b + 1) & 3], y4 = c2y[(b + 1) & 3];
                float fx = x4 - x3, fy = y4 - y3;
                float num   = fy * ex - fx * ey;
                float den_t = fx * (y1 - y3) - fy * (x1 - x3);
                float den_u = ex * (y1 - y3) - ey * (x1 - x3);
                bool ok = false;
                if (num != 0.0f) {
                    float t = den_t / num;
                    float u = -den_u / num;
                    ok = (t > 0.0f) && (t < 1.0f) && (u > 0.0f) && (u < 1.0f);
                }
                if (ok) {
                    float t2 = den_t / (num + EPSF);
                    float px = x1 + t2 * ex;
                    float py = y1 + t2 * ey;
                    vx[nv] = px; vy[nv] = py;
                    sx += px; sy += py;
                    nv++;
                }
            }
        }

        float inter = 0.0f;
        if (nv > 0) {
            float inv = 1.0f / (float)nv;   // nv>=1; reference uses max(nv,1)
            float mx = sx * inv, my = sy * inv;
            float ang[MAXV];
            for (int k = 0; k < nv; k++) {
                vx[k] -= mx;
                vy[k] -= my;
                ang[k] = atan2f(vy[k], vx[k]);
            }
            // stable insertion sort by angle (matches jnp.argsort stability)
            for (int k = 1; k < nv; k++) {
                float a = ang[k], x = vx[k], y = vy[k];
                int j = k - 1;
                while (j >= 0 && ang[j] > a) {
                    ang[j + 1] = ang[j];
                    vx[j + 1] = vx[j];
                    vy[j + 1] = vy[j];
                    j--;
                }
                ang[j + 1] = a; vx[j + 1] = x; vy[j + 1] = y;
            }
            // shoelace on centered, sorted vertices
            float cs = 0.0f;
            for (int k = 0; k < nv; k++) {
                int kn = (k + 1 == nv) ? 0 : k + 1;
                cs += vx[k] * vy[kn] - vy[k] * vx[kn];
            }
            inter = 0.5f * fabsf(cs);
        }

        float u2 = b1.w * b1.l + b2.w * b2.l - inter;
        float iou2d = inter / u2;
        float zo = fminf(b1.zmax, b2.zmax) - fmaxf(b1.zmin, b2.zmin);
        zo = fmaxf(zo, 0.0f);
        float inter3 = iou2d * u2 * zo;
        float u3 = b1.vol + b2.vol - inter3;
        float ious3 = inter3 / u3;
        float vol_inter = ious3 * u3;
        float r = (vol_inter + 1.0f) / (u3 + 1.0f);
        acc += -logf(r) * weight[i];
    }

    // block reduction (deterministic)
    __shared__ float sh[256];
    sh[threadIdx.x] = acc;
    __syncthreads();
#pragma unroll
    for (int o = 128; o > 0; o >>= 1) {
        if (threadIdx.x < o) sh[threadIdx.x] += sh[threadIdx.x + o];
        __syncthreads();
    }
    if (threadIdx.x == 0) g_partials[blockIdx.x] = sh[0];
}

__global__ void __launch_bounds__(256)
reduce_kernel(float* __restrict__ out, int nb) {
    __shared__ float sh[256];
    float s = 0.0f;
    for (int i = threadIdx.x; i < nb; i += 256) s += g_partials[i];
    sh[threadIdx.x] = s;
    __syncthreads();
#pragma unroll
    for (int o = 128; o > 0; o >>= 1) {
        if (threadIdx.x < o) sh[threadIdx.x] += sh[threadIdx.x + o];
        __syncthreads();
    }
    if (threadIdx.x == 0) out[0] = sh[0];
}

extern "C" void kernel_launch(void* const* d_in, const int* in_sizes, int n_in,
                              void* d_out, int out_size) {
    const float* pred   = (const float*)d_in[0];
    const float* target = (const float*)d_in[1];
    const float* weight = (const float*)d_in[2];
    float* out = (float*)d_out;

    int n = (n_in >= 3) ? in_sizes[2] : in_sizes[0] / 7;
    int nb = (n + 255) / 256;
    if (nb > NBLK) nb = NBLK;

    riou_kernel<<<nb, 256>>>(pred, target, weight, n);
    reduce_kernel<<<1, 256>>>(out, nb);
}

// round 10
// speedup vs baseline: 1.0442x; 1.0442x over previous
#include <cuda_runtime.h>
#include <math.h>

#define EPSF 1e-8f
#define MAXV 24
#define NBLK 4096

__device__ float g_partials[NBLK];
__device__ unsigned int g_count = 0;

struct Box2D {
    float X[4], Y[4];       // global-frame corners, reference order
    float area;             // w*l
    float zmin, zmax, vol;
};

__device__ __forceinline__ Box2D decode_box(const float* __restrict__ d) {
    float d0 = d[0], d1 = d[1], d2 = d[2], d3 = d[3], d4 = d[4], d5 = d[5];
    float th = d[6];
    float w = d0 + d3, l = d1 + d4, h = d2 + d5;
    float ox = 0.5f * (d3 - d0), oy = 0.5f * (d4 - d1), oz = 0.5f * (d5 - d2);
    float c = __cosf(th), s = __sinf(th);
    float cx = ox * c - oy * s;
    float cy = ox * s + oy * c;
    Box2D b;
    const float xs[4] = {0.5f, -0.5f, -0.5f, 0.5f};
    const float ys[4] = {0.5f, 0.5f, -0.5f, -0.5f};
#pragma unroll
    for (int k = 0; k < 4; k++) {
        float x4 = xs[k] * w, y4 = ys[k] * l;
        b.X[k] = x4 * c - y4 * s + cx;
        b.Y[k] = x4 * s + y4 * c + cy;
    }
    b.area = w * l;
    b.zmin = oz - 0.5f * h;
    b.zmax = oz + 0.5f * h;
    b.vol  = w * l * h;
    return b;
}

// Corners of P inside rectangle Q (reference box1_in_box2, division-free:
// p_ab in (-tol, 1+tol)  <=>  dot in (-tol*ab2, (1+tol)*ab2), ab2 > 0)
__device__ __forceinline__ void in_box_mask(const Box2D& P, const Box2D& Q, bool* m) {
    const float tol = 1e-6f;
    float ax = Q.X[0], ay = Q.Y[0];
    float abx = Q.X[1] - ax, aby = Q.Y[1] - ay;
    float adx = Q.X[3] - ax, ady = Q.Y[3] - ay;
    float ab2 = abx * abx + aby * aby;
    float ad2 = adx * adx + ady * ady;
    float ab_lo = -tol * ab2, ab_hi = (1.0f + tol) * ab2;
    float ad_lo = -tol * ad2, ad_hi = (1.0f + tol) * ad2;
#pragma unroll
    for (int i = 0; i < 4; i++) {
        float amx = P.X[i] - ax, amy = P.Y[i] - ay;
        float dab = abx * amx + aby * amy;
        float dad = adx * amx + ady * amy;
        m[i] = (dab > ab_lo) & (dab < ab_hi) & (dad > ad_lo) & (dad < ad_hi);
    }
}

// Monotone surrogate of atan2f(y, x): strictly increasing bijection
// (-pi, pi] -> (-2, 2], branch cut identical (negative x axis, sign of y via
// signbit so -0 maps to the -pi side exactly like atan2). Same sort order.
__device__ __forceinline__ float pangle(float x, float y) {
    float d = fabsf(x) + fabsf(y);
    float r = __fdividef(x, fmaxf(d, 1e-35f));
    return (__float_as_int(y) < 0) ? (r - 1.0f) : (1.0f - r);
}

__global__ void __launch_bounds__(256)
riou_kernel(const float* __restrict__ pred,
            const float* __restrict__ target,
            const float* __restrict__ weight,
            float* __restrict__ out,
            int n, int nb) {
    float acc = 0.0f;
    for (int i = blockIdx.x * blockDim.x + threadIdx.x; i < n;
         i += gridDim.x * blockDim.x) {
        Box2D b1 = decode_box(pred + (size_t)i * 7);
        Box2D b2 = decode_box(target + (size_t)i * 7);

        float zo = fminf(b1.zmax, b2.zmax) - fmaxf(b1.zmin, b2.zmin);
        zo = fmaxf(zo, 0.0f);

        float inter = 0.0f;
        if (zo > 0.0f) {   // if zo==0, inter3==0 regardless of polygon
            float vx[MAXV], vy[MAXV];
            int nv = 0;
            float sx = 0.0f, sy = 0.0f;

            bool m12[4], m21[4];
            in_box_mask(b1, b2, m12);
            in_box_mask(b2, b1, m21);
#pragma unroll
            for (int k = 0; k < 4; k++)
                if (m12[k]) { vx[nv] = b1.X[k]; vy[nv] = b1.Y[k]; sx += b1.X[k]; sy += b1.Y[k]; nv++; }
#pragma unroll
            for (int k = 0; k < 4; k++)
                if (m21[k]) { vx[nv] = b2.X[k]; vy[nv] = b2.Y[k]; sx += b2.X[k]; sy += b2.Y[k]; nv++; }

            // 16 edge-edge crossings; masks via sign products (no division):
            //  t = dt/num in (0,1)  <=>  dt*num>0  &&  (dt-num)*num<0
            //  u = -du/num in (0,1) <=>  du*num<0  &&  (du+num)*num>0
#pragma unroll
            for (int a = 0; a < 4; a++) {
                float x1 = b1.X[a], y1 = b1.Y[a];
                float ex = b1.X[(a + 1) & 3] - x1;
                float ey = b1.Y[(a + 1) & 3] - y1;
#pragma unroll
                for (int b = 0; b < 4; b++) {
                    float x3 = b2.X[b], y3 = b2.Y[b];
                    float fx = b2.X[(b + 1) & 3] - x3;
                    float fy = b2.Y[(b + 1) & 3] - y3;
                    float rx = y1 - y3, ry = x1 - x3;
                    float num = fy * ex - fx * ey;
                    float dt  = fx * rx - fy * ry;
                    float du  = ex * rx - ey * ry;
                    bool ok = (dt * num > 0.0f) && ((dt - num) * num < 0.0f) &&
                              (du * num < 0.0f) && ((du + num) * num > 0.0f);
                    if (ok) {
                        float t2 = __fdividef(dt, num + EPSF);   // reference's t2
                        float px = x1 + t2 * ex;
                        float py = y1 + t2 * ey;
                        vx[nv] = px; vy[nv] = py;
                        sx += px; sy += py;
                        nv++;
                    }
                }
            }

            if (nv >= 3) {
                float inv = __fdividef(1.0f, (float)nv);
                float mx = sx * inv, my = sy * inv;
                float ang[MAXV];
                for (int k = 0; k < nv; k++) {
                    vx[k] -= mx;
                    vy[k] -= my;
                    ang[k] = pangle(vx[k], vy[k]);
                }
                // stable insertion sort (same order as argsort over atan2)
                for (int k = 1; k < nv; k++) {
                    float a = ang[k], x = vx[k], y = vy[k];
                    int j = k - 1;
                    while (j >= 0 && ang[j] > a) {
                        ang[j + 1] = ang[j];
                        vx[j + 1] = vx[j];
                        vy[j + 1] = vy[j];
                        j--;
                    }
                    ang[j + 1] = a; vx[j + 1] = x; vy[j + 1] = y;
                }
                float cs = 0.0f;
                for (int k = 0; k < nv; k++) {
                    int kn = (k + 1 == nv) ? 0 : k + 1;
                    cs += vx[k] * vy[kn] - vy[k] * vx[kn];
                }
                inter = 0.5f * fabsf(cs);
            }
        }

        // 3D IoU loss (identical formula chain to passing R1 kernel)
        float u2 = b1.area + b2.area - inter;
        float iou2d = __fdividef(inter, u2);
        float inter3 = iou2d * u2 * zo;
        float u3 = b1.vol + b2.vol - inter3;
        float r = __fdividef(inter3 + 1.0f, u3 + 1.0f);
        acc += -__logf(r) * weight[i];
    }

    // ---- intra-block reduction ----
    __shared__ float warp_s[8];
#pragma unroll
    for (int o = 16; o > 0; o >>= 1)
        acc += __shfl_down_sync(0xffffffffu, acc, o);
    int lane = threadIdx.x & 31, wid = threadIdx.x >> 5;
    if (lane == 0) warp_s[wid] = acc;
    __syncthreads();
    if (wid == 0) {
        float v = (lane < 8) ? warp_s[lane] : 0.0f;
#pragma unroll
        for (int o = 4; o > 0; o >>= 1)
            v += __shfl_down_sync(0xffffffffu, v, o);
        if (lane == 0) __stcg(&g_partials[blockIdx.x], v);   // L2-coherent store
    }

    // ---- last-block-done final reduction (deterministic order) ----
    __shared__ bool is_last;
    __threadfence();
    if (threadIdx.x == 0) {
        unsigned int c = atomicAdd(&g_count, 1u);
        is_last = (c == (unsigned int)(nb - 1));
    }
    __syncthreads();
    if (is_last) {
        float s = 0.0f;
        for (int k = threadIdx.x; k < nb; k += 256)
            s += __ldcg(&g_partials[k]);                     // L2-coherent load
#pragma unroll
        for (int o = 16; o > 0; o >>= 1)
            s += __shfl_down_sync(0xffffffffu, s, o);
        if (lane == 0) warp_s[wid] = s;
        __syncthreads();
        if (wid == 0) {
            float v = (lane < 8) ? warp_s[lane] : 0.0f;
#pragma unroll
            for (int o = 4; o > 0; o >>= 1)
                v += __shfl_down_sync(0xffffffffu, v, o);
            if (lane == 0) {
                out[0] = v;
                g_count = 0;   // reset for next launch / graph replay
            }
        }
    }
}

extern "C" void kernel_launch(void* const* d_in, const int* in_sizes, int n_in,
                              void* d_out, int out_size) {
    const float* pred   = (const float*)d_in[0];
    const float* target = (const float*)d_in[1];
    const float* weight = (const float*)d_in[2];
    float* out = (float*)d_out;

    int n = (n_in >= 3) ? in_sizes[2] : in_sizes[0] / 7;
    int nb = (n + 255) / 256;
    if (nb > NBLK) nb = NBLK;   // n=250000 -> 977 blocks; grid-stride covers any excess

    riou_kernel<<<nb, 256>>>(pred, target, weight, out, n, nb);
}

// round 13
// speedup vs baseline: 1.0812x; 1.0354x over previous
#include <cuda_runtime.h>
#include <math.h>

#define EPSF 1e-8f
#define MAXV 24
#define NBLK 4096

__device__ float g_partials[NBLK];
__device__ unsigned int g_count = 0;

struct Box2D {
    float X[4], Y[4];
    float area;
    float zmin, zmax, vol;
};

__device__ __forceinline__ Box2D decode_box(const float* __restrict__ d) {
    float d0 = d[0], d1 = d[1], d2 = d[2], d3 = d[3], d4 = d[4], d5 = d[5];
    float th = d[6];
    float w = d0 + d3, l = d1 + d4, h = d2 + d5;
    float ox = 0.5f * (d3 - d0), oy = 0.5f * (d4 - d1), oz = 0.5f * (d5 - d2);
    float c = __cosf(th), s = __sinf(th);
    float cx = ox * c - oy * s;
    float cy = ox * s + oy * c;
    Box2D b;
    const float xs[4] = {0.5f, -0.5f, -0.5f, 0.5f};
    const float ys[4] = {0.5f, 0.5f, -0.5f, -0.5f};
#pragma unroll
    for (int k = 0; k < 4; k++) {
        float x4 = xs[k] * w, y4 = ys[k] * l;
        b.X[k] = x4 * c - y4 * s + cx;
        b.Y[k] = x4 * s + y4 * c + cy;
    }
    b.area = w * l;
    b.zmin = oz - 0.5f * h;
    b.zmax = oz + 0.5f * h;
    b.vol  = w * l * h;
    return b;
}

// Division-free reference containment test (verified in R10, rel_err 0.0)
__device__ __forceinline__ void in_box_mask(const Box2D& P, const Box2D& Q, bool* m) {
    const float tol = 1e-6f;
    float ax = Q.X[0], ay = Q.Y[0];
    float abx = Q.X[1] - ax, aby = Q.Y[1] - ay;
    float adx = Q.X[3] - ax, ady = Q.Y[3] - ay;
    float ab2 = abx * abx + aby * aby;
    float ad2 = adx * adx + ady * ady;
    float ab_lo = -tol * ab2, ab_hi = (1.0f + tol) * ab2;
    float ad_lo = -tol * ad2, ad_hi = (1.0f + tol) * ad2;
#pragma unroll
    for (int i = 0; i < 4; i++) {
        float amx = P.X[i] - ax, amy = P.Y[i] - ay;
        float dab = abx * amx + aby * amy;
        float dad = adx * amx + ady * amy;
        m[i] = (dab > ab_lo) & (dab < ab_hi) & (dad > ad_lo) & (dad < ad_hi);
    }
}

// Monotone surrogate of atan2f (verified in R10): same sort order.
__device__ __forceinline__ float pangle(float x, float y) {
    float d = fabsf(x) + fabsf(y);
    float r = __fdividef(x, fmaxf(d, 1e-35f));
    return (__float_as_int(y) < 0) ? (r - 1.0f) : (1.0f - r);
}

// Ordered-float encoding: monotone map float -> uint32; -0 and +0 map equal
// (matches IEEE-equal treatment in the reference's stable argsort).
__device__ __forceinline__ unsigned int fkey(float f) {
    unsigned int b = __float_as_uint(f);
    if (b == 0x80000000u) b = 0u;                       // -0 -> +0
    return (b & 0x80000000u) ? ~b : (b | 0x80000000u);
}

__global__ void __launch_bounds__(256)
riou_kernel(const float* __restrict__ pred,
            const float* __restrict__ target,
            const float* __restrict__ weight,
            float* __restrict__ out,
            int n, int nb) {
    __shared__ float s_p[256 * 7];
    __shared__ float s_t[256 * 7];
    const int tid = threadIdx.x;
    float acc = 0.0f;

    for (int ib = blockIdx.x; ib * 256 < n; ib += gridDim.x) {
        // ---- coalesced stage of this block's 7-float records into smem ----
        {
            size_t base = (size_t)ib * 256 * 7;
            size_t total = (size_t)n * 7;
#pragma unroll
            for (int j = 0; j < 7; j++) {
                size_t g = base + (size_t)j * 256 + tid;
                bool ok = g < total;
                s_p[j * 256 + tid] = ok ? pred[g]   : 0.0f;
                s_t[j * 256 + tid] = ok ? target[g] : 0.0f;
            }
        }
        __syncthreads();

        int i = ib * 256 + tid;
        if (i < n) {
            Box2D b1 = decode_box(s_p + tid * 7);
            Box2D b2 = decode_box(s_t + tid * 7);

            float zo = fminf(b1.zmax, b2.zmax) - fmaxf(b1.zmin, b2.zmin);
            zo = fmaxf(zo, 0.0f);

            float inter = 0.0f;
            if (zo > 0.0f) {
                float2 vtx[MAXV];
                unsigned long long key[MAXV];
                int nv = 0;
                float sx = 0.0f, sy = 0.0f;

                bool m12[4], m21[4];
                in_box_mask(b1, b2, m12);
                in_box_mask(b2, b1, m21);
#pragma unroll
                for (int k = 0; k < 4; k++)
                    if (m12[k]) { vtx[nv] = make_float2(b1.X[k], b1.Y[k]); sx += b1.X[k]; sy += b1.Y[k]; nv++; }
#pragma unroll
                for (int k = 0; k < 4; k++)
                    if (m21[k]) { vtx[nv] = make_float2(b2.X[k], b2.Y[k]); sx += b2.X[k]; sy += b2.Y[k]; nv++; }

                // hoisted box2 edge vectors
                float fxv[4], fyv[4];
#pragma unroll
                for (int b = 0; b < 4; b++) {
                    fxv[b] = b2.X[(b + 1) & 3] - b2.X[b];
                    fyv[b] = b2.Y[(b + 1) & 3] - b2.Y[b];
                }

                // 16 edge crossings, division-free masks (verified in R10)
#pragma unroll
                for (int a = 0; a < 4; a++) {
                    float x1 = b1.X[a], y1 = b1.Y[a];
                    float ex = b1.X[(a + 1) & 3] - x1;
                    float ey = b1.Y[(a + 1) & 3] - y1;
#pragma unroll
                    for (int b = 0; b < 4; b++) {
                        float x3 = b2.X[b], y3 = b2.Y[b];
                        float fx = fxv[b], fy = fyv[b];
                        float rx = y1 - y3, ry = x1 - x3;
                        float num = fy * ex - fx * ey;
                        float dt  = fx * rx - fy * ry;
                        float du  = ex * rx - ey * ry;
                        bool ok = (dt * num > 0.0f) && ((dt - num) * num < 0.0f) &&
                                  (du * num < 0.0f) && ((du + num) * num > 0.0f);
                        if (ok) {
                            float t2 = __fdividef(dt, num + EPSF);
                            float px = x1 + t2 * ex;
                            float py = y1 + t2 * ey;
                            vtx[nv] = make_float2(px, py);
                            sx += px; sy += py;
                            nv++;
                        }
                    }
                }

                if (nv >= 3) {
                    float inv = __fdividef(1.0f, (float)nv);
                    float mx = sx * inv, my = sy * inv;

                    // build 64-bit stable sort keys: (ordered-angle << 32) | idx
                    for (int k = 0; k < nv; k++) {
                        float2 v = vtx[k];
                        float ang = pangle(v.x - mx, v.y - my);
                        key[k] = ((unsigned long long)fkey(ang) << 32) | (unsigned int)k;
                    }
                    // insertion sort on 8-byte keys (stable via idx low bits)
                    for (int k = 1; k < nv; k++) {
                        unsigned long long kk = key[k];
                        int j = k - 1;
                        while (j >= 0 && key[j] > kk) {
                            key[j + 1] = key[j];
                            j--;
                        }
                        key[j + 1] = kk;
                    }
                    // shoelace on centered vertices in sorted order
                    float cs = 0.0f;
                    float2 first = make_float2(0.f, 0.f), prev = make_float2(0.f, 0.f);
                    for (int k = 0; k < nv; k++) {
                        int id = (int)(key[k] & 0xFFu);
                        float2 v = vtx[id];
                        v.x -= mx; v.y -= my;
                        if (k == 0) first = v;
                        else cs += prev.x * v.y - prev.y * v.x;
                        prev = v;
                    }
                    cs += prev.x * first.y - prev.y * first.x;
                    inter = 0.5f * fabsf(cs);
                }
            }

            // 3D IoU loss — identical chain to verified R10
            float u2 = b1.area + b2.area - inter;
            float iou2d = __fdividef(inter, u2);
            float inter3 = iou2d * u2 * zo;
            float u3 = b1.vol + b2.vol - inter3;
            float r = __fdividef(inter3 + 1.0f, u3 + 1.0f);
            acc += -__logf(r) * weight[i];
        }
        __syncthreads();
    }

    // ---- intra-block reduction (verbatim from R10, verified) ----
    __shared__ float warp_s[8];
#pragma unroll
    for (int o = 16; o > 0; o >>= 1)
        acc += __shfl_down_sync(0xffffffffu, acc, o);
    int lane = threadIdx.x & 31, wid = threadIdx.x >> 5;
    if (lane == 0) warp_s[wid] = acc;
    __syncthreads();
    if (wid == 0) {
        float v = (lane < 8) ? warp_s[lane] : 0.0f;
#pragma unroll
        for (int o = 4; o > 0; o >>= 1)
            v += __shfl_down_sync(0xffffffffu, v, o);
        if (lane == 0) __stcg(&g_partials[blockIdx.x], v);
    }

    // ---- last-block-done final reduction (verbatim from R10, verified) ----
    __shared__ bool is_last;
    __threadfence();
    if (threadIdx.x == 0) {
        unsigned int c = atomicAdd(&g_count, 1u);
        is_last = (c == (unsigned int)(nb - 1));
    }
    __syncthreads();
    if (is_last) {
        float s = 0.0f;
        for (int k = threadIdx.x; k < nb; k += 256)
            s += __ldcg(&g_partials[k]);
#pragma unroll
        for (int o = 16; o > 0; o >>= 1)
            s += __shfl_down_sync(0xffffffffu, s, o);
        if (lane == 0) warp_s[wid] = s;
        __syncthreads();
        if (wid == 0) {
            float v = (lane < 8) ? warp_s[lane] : 0.0f;
#pragma unroll
            for (int o = 4; o > 0; o >>= 1)
                v += __shfl_down_sync(0xffffffffu, v, o);
            if (lane == 0) {
                out[0] = v;
                g_count = 0;
            }
        }
    }
}

extern "C" void kernel_launch(void* const* d_in, const int* in_sizes, int n_in,
                              void* d_out, int out_size) {
    const float* pred   = (const float*)d_in[0];
    const float* target = (const float*)d_in[1];
    const float* weight = (const float*)d_in[2];
    float* out = (float*)d_out;

    int n = (n_in >= 3) ? in_sizes[2] : in_sizes[0] / 7;
    int nb = (n + 255) / 256;
    if (nb > NBLK) nb = NBLK;   // grid-stride staging loop covers any excess

    riou_kernel<<<nb, 256>>>(pred, target, weight, out, n, nb);
}